// round 3
// baseline (speedup 1.0000x reference)
#include <cuda_runtime.h>
#include <cuda_bf16.h>
#include <cstdint>

#define T_DIM 12
#define B_DIM 16
#define N_DIM 2048
#define D_DIM 128
#define TD    1536   // T_DIM * D_DIM
#define CAND  8      // candidates kept per row for exact refinement

// Scratch (device globals: allocation-free per harness rules)
__device__ __nv_bfloat16 g_xn[(size_t)B_DIM * N_DIM * TD];      // ~100 MB  (bf16 normalized)
__device__ float         g_xf[(size_t)B_DIM * N_DIM * TD];      // ~201 MB  (fp32 normalized)
__device__ float         g_dist[(size_t)B_DIM * N_DIM * N_DIM]; // ~268 MB  (approx sims)
__device__ int           g_cand[(size_t)B_DIM * N_DIM * CAND];  // 1 MB

// ---------------------------------------------------------------------------
// Kernel 1: permute [T,B,N,D] -> [B,N,T*D], row-normalize; write fp32 + bf16
// ---------------------------------------------------------------------------
__global__ void k_normalize(const float* __restrict__ x) {
    int bn = blockIdx.x;
    int b = bn >> 11, n = bn & (N_DIM - 1);
    int d = threadIdx.x;  // 128 threads = D_DIM
    float vals[T_DIM];
    float ss = 0.f;
#pragma unroll
    for (int t = 0; t < T_DIM; ++t) {
        float v = x[(((size_t)t * B_DIM + b) * N_DIM + n) * D_DIM + d];
        vals[t] = v;
        ss += v * v;
    }
#pragma unroll
    for (int off = 16; off; off >>= 1) ss += __shfl_xor_sync(0xffffffffu, ss, off);
    __shared__ float sred[4];
    int lane = d & 31, wid = d >> 5;
    if (lane == 0) sred[wid] = ss;
    __syncthreads();
    float tot = sred[0] + sred[1] + sred[2] + sred[3];
    float rn = 1.0f / sqrtf(tot);   // IEEE-rounded, not MUFU approximation
    size_t base = (size_t)(b * N_DIM + n) * TD + d;
#pragma unroll
    for (int t = 0; t < T_DIM; ++t) {
        float v = vals[t] * rn;
        g_xf[base + (size_t)t * D_DIM] = v;
        g_xn[base + (size_t)t * D_DIM] = __float2bfloat16(v);
    }
}

// ---------------------------------------------------------------------------
// Kernel 2: zero-fill output (poisoned to 0xAA by the harness)
// ---------------------------------------------------------------------------
__global__ void k_zero(float4* __restrict__ out, size_t n4) {
    size_t i = (size_t)blockIdx.x * blockDim.x + threadIdx.x;
    size_t stride = (size_t)gridDim.x * blockDim.x;
    float4 z = make_float4(0.f, 0.f, 0.f, 0.f);
    for (; i < n4; i += stride) out[i] = z;
}

// ---------------------------------------------------------------------------
// Kernel 3: batched GEMM  dist[b] = xn[b] * xn[b]^T  (bf16 in, fp32 accum)
// CTA tile 128x128x(K=64), 8 warps (2x4), mma.sync m16n8k16, cp.async 2-stage,
// XOR-swizzled 128B smem rows (conflict-free ldmatrix).
// ---------------------------------------------------------------------------
#define BM 128
#define BN 128
#define BK 64
#define NKT (TD / BK)  // 24

__device__ __forceinline__ void cp16(uint32_t saddr, const void* gaddr) {
    asm volatile("cp.async.cg.shared.global [%0], [%1], 16;\n" :: "r"(saddr), "l"(gaddr));
}

__global__ void __launch_bounds__(256) k_gemm() {
    extern __shared__ __align__(128) __nv_bfloat16 sm[];
    uint32_t smem = (uint32_t)__cvta_generic_to_shared(sm);
    // byte layout: A s0 [0,16K) A s1 [16K,32K) B s0 [32K,48K) B s1 [48K,64K)
    int b = blockIdx.z;
    int mBase = blockIdx.y * BM, nBase = blockIdx.x * BN;
    const __nv_bfloat16* Ag = g_xn + (size_t)b * N_DIM * TD + (size_t)mBase * TD;
    const __nv_bfloat16* Bg = g_xn + (size_t)b * N_DIM * TD + (size_t)nBase * TD;
    int tid = threadIdx.x;
    int lane = tid & 31, wid = tid >> 5;
    int warpM = wid & 1, warpN = wid >> 1;  // 2 x 4 warps -> warp tile 64x32

    float acc[4][4][4];
#pragma unroll
    for (int mi = 0; mi < 4; ++mi)
#pragma unroll
        for (int ni = 0; ni < 4; ++ni)
#pragma unroll
            for (int r = 0; r < 4; ++r) acc[mi][ni][r] = 0.f;

    auto issue = [&](int stage, int kt) {
        int k0 = kt * BK;
#pragma unroll
        for (int i = 0; i < 4; ++i) {
            int idx = tid + i * 256;        // 0..1023
            int row = idx >> 3, c = idx & 7; // 8 x 16B granules per 128B row
            uint32_t soff = (uint32_t)(row * 128 + ((c ^ (row & 7)) << 4));
            cp16(smem + stage * 16384 + soff, Ag + (size_t)row * TD + k0 + c * 8);
            cp16(smem + 32768 + stage * 16384 + soff, Bg + (size_t)row * TD + k0 + c * 8);
        }
    };

    issue(0, 0);
    asm volatile("cp.async.commit_group;\n");

    for (int kt = 0; kt < NKT; ++kt) {
        asm volatile("cp.async.wait_group 0;\n");
        __syncthreads();
        if (kt + 1 < NKT) {
            issue((kt + 1) & 1, kt + 1);
            asm volatile("cp.async.commit_group;\n");
        }
        int s = kt & 1;
#pragma unroll
        for (int kk = 0; kk < 4; ++kk) {  // 4 k-steps of 16
            uint32_t af[4][4], bf[4][2];
#pragma unroll
            for (int mi = 0; mi < 4; ++mi) {
                int r = warpM * 64 + mi * 16 + (lane & 15);
                int g = kk * 2 + (lane >> 4);
                uint32_t addr = smem + s * 16384 + r * 128 + ((g ^ (r & 7)) << 4);
                asm volatile("ldmatrix.sync.aligned.m8n8.x4.shared.b16 {%0,%1,%2,%3}, [%4];\n"
                    : "=r"(af[mi][0]), "=r"(af[mi][1]), "=r"(af[mi][2]), "=r"(af[mi][3])
                    : "r"(addr));
            }
#pragma unroll
            for (int ni = 0; ni < 4; ++ni) {
                int r = warpN * 32 + ni * 8 + (lane & 7);
                int g = kk * 2 + ((lane >> 3) & 1);
                uint32_t addr = smem + 32768 + s * 16384 + r * 128 + ((g ^ (r & 7)) << 4);
                asm volatile("ldmatrix.sync.aligned.m8n8.x2.shared.b16 {%0,%1}, [%2];\n"
                    : "=r"(bf[ni][0]), "=r"(bf[ni][1]) : "r"(addr));
            }
#pragma unroll
            for (int mi = 0; mi < 4; ++mi)
#pragma unroll
                for (int ni = 0; ni < 4; ++ni) {
                    asm volatile(
                        "mma.sync.aligned.m16n8k16.row.col.f32.bf16.bf16.f32 "
                        "{%0,%1,%2,%3}, {%4,%5,%6,%7}, {%8,%9}, {%0,%1,%2,%3};\n"
                        : "+f"(acc[mi][ni][0]), "+f"(acc[mi][ni][1]),
                          "+f"(acc[mi][ni][2]), "+f"(acc[mi][ni][3])
                        : "r"(af[mi][0]), "r"(af[mi][1]), "r"(af[mi][2]), "r"(af[mi][3]),
                          "r"(bf[ni][0]), "r"(bf[ni][1]));
                }
        }
    }

    float* Cg = g_dist + ((size_t)b * N_DIM + mBase) * N_DIM + nBase;
#pragma unroll
    for (int mi = 0; mi < 4; ++mi)
#pragma unroll
        for (int ni = 0; ni < 4; ++ni) {
            int r0 = warpM * 64 + mi * 16 + (lane >> 2);
            int c0 = warpN * 32 + ni * 8 + 2 * (lane & 3);
            float2 v01 = make_float2(acc[mi][ni][0], acc[mi][ni][1]);
            float2 v23 = make_float2(acc[mi][ni][2], acc[mi][ni][3]);
            *(float2*)(Cg + (size_t)r0 * N_DIM + c0) = v01;
            *(float2*)(Cg + (size_t)(r0 + 8) * N_DIM + c0) = v23;
        }
}

// ---------------------------------------------------------------------------
// Kernel 4: warp-per-row approximate top-8 candidate selection (indices only)
// ---------------------------------------------------------------------------
__global__ void __launch_bounds__(256) k_topk(void) {
    __shared__ float sv[8][32 * CAND];
    __shared__ int   si[8][32 * CAND];
    int w = threadIdx.x >> 5;
    int lane = threadIdx.x & 31;
    int gw = blockIdx.x * 8 + w;              // global row id over B*N
    int b = gw >> 11, r = gw & (N_DIM - 1);
    const float* row = g_dist + ((size_t)b * N_DIM + r) * N_DIM;

    float tv[CAND];
    int   ti[CAND];
#pragma unroll
    for (int s = 0; s < CAND; ++s) { tv[s] = -3.4e38f; ti[s] = 0; }

    for (int j = lane; j < N_DIM; j += 32) {
        float val = row[j];
        if (val > tv[CAND - 1]) {
            tv[CAND - 1] = val; ti[CAND - 1] = j;
#pragma unroll
            for (int s = CAND - 1; s > 0; --s) {
                if (tv[s] > tv[s - 1]) {
                    float a = tv[s]; tv[s] = tv[s - 1]; tv[s - 1] = a;
                    int   c = ti[s]; ti[s] = ti[s - 1]; ti[s - 1] = c;
                }
            }
        }
    }
#pragma unroll
    for (int s = 0; s < CAND; ++s) {
        sv[w][lane * CAND + s] = tv[s];
        si[w][lane * CAND + s] = ti[s];
    }
    __syncwarp();

    if (lane == 0) {
        float mv[CAND];
        int   mi[CAND];
#pragma unroll
        for (int s = 0; s < CAND; ++s) { mv[s] = -3.4e38f; mi[s] = 0; }
        for (int c = 0; c < 32 * CAND; ++c) {
            float val = sv[w][c]; int jj = si[w][c];
            if (val > mv[CAND - 1]) {
                mv[CAND - 1] = val; mi[CAND - 1] = jj;
#pragma unroll
                for (int s = CAND - 1; s > 0; --s) {
                    if (mv[s] > mv[s - 1]) {
                        float a = mv[s]; mv[s] = mv[s - 1]; mv[s - 1] = a;
                        int   d2 = mi[s]; mi[s] = mi[s - 1]; mi[s - 1] = d2;
                    }
                }
            }
        }
#pragma unroll
        for (int s = 0; s < CAND; ++s) g_cand[(size_t)gw * CAND + s] = mi[s];
    }
}

// ---------------------------------------------------------------------------
// Kernel 5: exact fp32 re-ranking of the 8 candidates + symmetric scatter.
// One block per row; warp w recomputes dot(row, cand[w]) exactly in fp32.
// Lane-strided sum + shfl tree is bit-identical for (r,j) and (j,r), so the
// symmetric halves add to exactly the full value when both rows pick each
// other (matches reference semantics to fp32 noise ~1e-7).
// ---------------------------------------------------------------------------
__global__ void __launch_bounds__(256) k_refine(float* __restrict__ out) {
    int rowid = blockIdx.x;
    int b = rowid >> 11, r = rowid & (N_DIM - 1);
    __shared__ float srow[TD];
    __shared__ float sdot[CAND];
    __shared__ int   sjj[CAND];
    const float* xr = g_xf + (size_t)rowid * TD;
    for (int i = threadIdx.x; i < TD; i += 256) srow[i] = xr[i];
    __syncthreads();

    int w = threadIdx.x >> 5, lane = threadIdx.x & 31;
    int j = g_cand[(size_t)rowid * CAND + w];
    const float* xj = g_xf + ((size_t)(b << 11) + j) * TD;
    float s = 0.f;
#pragma unroll
    for (int i = 0; i < TD / 32; ++i)
        s = fmaf(srow[lane + i * 32], xj[lane + i * 32], s);
#pragma unroll
    for (int o = 16; o; o >>= 1) s += __shfl_xor_sync(0xffffffffu, s, o);
    if (lane == 0) { sdot[w] = s; sjj[w] = j; }
    __syncthreads();

    if (threadIdx.x == 0) {
        float tv[5]; int ti[5];
#pragma unroll
        for (int q = 0; q < 5; ++q) { tv[q] = -3.4e38f; ti[q] = 0; }
        for (int c = 0; c < CAND; ++c) {
            float val = sdot[c]; int jj = sjj[c];
            if (val > tv[4]) {
                tv[4] = val; ti[4] = jj;
#pragma unroll
                for (int q = 4; q > 0; --q) {
                    if (tv[q] > tv[q - 1]) {
                        float a = tv[q]; tv[q] = tv[q - 1]; tv[q - 1] = a;
                        int   d2 = ti[q]; ti[q] = ti[q - 1]; ti[q - 1] = d2;
                    }
                }
            }
        }
#pragma unroll
        for (int q = 0; q < 5; ++q) {
            float val = tv[q];
            int jj = ti[q];
            float lv = (val >= 0.f) ? val : 0.01f * val;  // leaky_relu
            float wgt = lv * 0.5f;                        // symmetric halves
            atomicAdd(out + ((size_t)b * N_DIM + r) * N_DIM + jj, wgt);
            atomicAdd(out + ((size_t)b * N_DIM + jj) * N_DIM + r, wgt);
        }
    }
}

// ---------------------------------------------------------------------------
extern "C" void kernel_launch(void* const* d_in, const int* in_sizes, int n_in,
                              void* d_out, int out_size) {
    const float* x = (const float*)d_in[0];
    float* out = (float*)d_out;

    k_normalize<<<B_DIM * N_DIM, 128>>>(x);

    size_t n4 = (size_t)B_DIM * N_DIM * N_DIM / 4;
    k_zero<<<8192, 256>>>((float4*)out, n4);

    cudaFuncSetAttribute(k_gemm, cudaFuncAttributeMaxDynamicSharedMemorySize, 65536);
    k_gemm<<<dim3(N_DIM / BN, N_DIM / BM, B_DIM), 256, 65536>>>();

    k_topk<<<(B_DIM * N_DIM) / 8, 256>>>();

    k_refine<<<B_DIM * N_DIM, 256>>>(out);
}

// round 4
// speedup vs baseline: 1.3990x; 1.3990x over previous
#include <cuda_runtime.h>
#include <cuda_bf16.h>
#include <cstdint>

#define T_DIM 12
#define B_DIM 16
#define N_DIM 2048
#define D_DIM 128
#define TD    1536   // T_DIM * D_DIM
#define CAND  8      // candidates kept per row for exact refinement

// Scratch (device globals: allocation-free per harness rules)
__device__ __nv_bfloat16 g_xn[(size_t)B_DIM * N_DIM * TD];      // ~100 MB  (bf16 normalized)
__device__ float         g_xf[(size_t)B_DIM * N_DIM * TD];      // ~201 MB  (fp32 normalized)
__device__ float         g_dist[(size_t)B_DIM * N_DIM * N_DIM]; // ~268 MB  (approx sims)
__device__ int           g_cand[(size_t)B_DIM * N_DIM * CAND];  // 1 MB

// ---------------------------------------------------------------------------
// Kernel 1: permute [T,B,N,D] -> [B,N,T*D], row-normalize; write fp32 + bf16
// ---------------------------------------------------------------------------
__global__ void k_normalize(const float* __restrict__ x) {
    int bn = blockIdx.x;
    int b = bn >> 11, n = bn & (N_DIM - 1);
    int d = threadIdx.x;  // 128 threads = D_DIM
    float vals[T_DIM];
    float ss = 0.f;
#pragma unroll
    for (int t = 0; t < T_DIM; ++t) {
        float v = x[(((size_t)t * B_DIM + b) * N_DIM + n) * D_DIM + d];
        vals[t] = v;
        ss += v * v;
    }
#pragma unroll
    for (int off = 16; off; off >>= 1) ss += __shfl_xor_sync(0xffffffffu, ss, off);
    __shared__ float sred[4];
    int lane = d & 31, wid = d >> 5;
    if (lane == 0) sred[wid] = ss;
    __syncthreads();
    float tot = sred[0] + sred[1] + sred[2] + sred[3];
    float rn = 1.0f / sqrtf(tot);   // IEEE-rounded, not MUFU approximation
    size_t base = (size_t)(b * N_DIM + n) * TD + d;
#pragma unroll
    for (int t = 0; t < T_DIM; ++t) {
        float v = vals[t] * rn;
        g_xf[base + (size_t)t * D_DIM] = v;
        g_xn[base + (size_t)t * D_DIM] = __float2bfloat16(v);
    }
}

// ---------------------------------------------------------------------------
// Kernel 2: zero-fill output (poisoned to 0xAA by the harness)
// ---------------------------------------------------------------------------
__global__ void k_zero(float4* __restrict__ out, size_t n4) {
    size_t i = (size_t)blockIdx.x * blockDim.x + threadIdx.x;
    size_t stride = (size_t)gridDim.x * blockDim.x;
    float4 z = make_float4(0.f, 0.f, 0.f, 0.f);
    for (; i < n4; i += stride) out[i] = z;
}

// ---------------------------------------------------------------------------
// Kernel 3: batched symmetric GEMM  dist[b] = xn[b] * xn[b]^T
// Only upper-triangular CTA tiles computed (136 of 256 per batch); off-diagonal
// tiles are written twice (direct + transposed via smem staging).
// ---------------------------------------------------------------------------
#define BM 128
#define BN 128
#define BK 64
#define NKT (TD / BK)  // 24
#define NTILE (N_DIM / BM)           // 16
#define NUT (NTILE * (NTILE + 1) / 2) // 136
#define SMEM_BYTES (128 * 132 * 4)   // 67584 (> 65536 mainloop use)

__device__ __forceinline__ void cp16(uint32_t saddr, const void* gaddr) {
    asm volatile("cp.async.cg.shared.global [%0], [%1], 16;\n" :: "r"(saddr), "l"(gaddr));
}

__global__ void __launch_bounds__(256) k_gemm() {
    extern __shared__ __align__(128) __nv_bfloat16 sm[];
    uint32_t smem = (uint32_t)__cvta_generic_to_shared(sm);
    // byte layout: A s0 [0,16K) A s1 [16K,32K) B s0 [32K,48K) B s1 [48K,64K)
    int b = blockIdx.z;
    // decode upper-triangular tile index -> (mb, nb), nb >= mb
    int t = blockIdx.x, mb = 0;
    while (t >= NTILE - mb) { t -= NTILE - mb; ++mb; }
    int nb = mb + t;
    int mBase = mb * BM, nBase = nb * BN;

    const __nv_bfloat16* Ag = g_xn + (size_t)b * N_DIM * TD + (size_t)mBase * TD;
    const __nv_bfloat16* Bg = g_xn + (size_t)b * N_DIM * TD + (size_t)nBase * TD;
    int tid = threadIdx.x;
    int lane = tid & 31, wid = tid >> 5;
    int warpM = wid & 1, warpN = wid >> 1;  // 2 x 4 warps -> warp tile 64x32

    float acc[4][4][4];
#pragma unroll
    for (int mi = 0; mi < 4; ++mi)
#pragma unroll
        for (int ni = 0; ni < 4; ++ni)
#pragma unroll
            for (int r = 0; r < 4; ++r) acc[mi][ni][r] = 0.f;

    auto issue = [&](int stage, int kt) {
        int k0 = kt * BK;
#pragma unroll
        for (int i = 0; i < 4; ++i) {
            int idx = tid + i * 256;        // 0..1023
            int row = idx >> 3, c = idx & 7; // 8 x 16B granules per 128B row
            uint32_t soff = (uint32_t)(row * 128 + ((c ^ (row & 7)) << 4));
            cp16(smem + stage * 16384 + soff, Ag + (size_t)row * TD + k0 + c * 8);
            cp16(smem + 32768 + stage * 16384 + soff, Bg + (size_t)row * TD + k0 + c * 8);
        }
    };

    issue(0, 0);
    asm volatile("cp.async.commit_group;\n");

    for (int kt = 0; kt < NKT; ++kt) {
        asm volatile("cp.async.wait_group 0;\n");
        __syncthreads();
        if (kt + 1 < NKT) {
            issue((kt + 1) & 1, kt + 1);
            asm volatile("cp.async.commit_group;\n");
        }
        int s = kt & 1;
#pragma unroll
        for (int kk = 0; kk < 4; ++kk) {  // 4 k-steps of 16
            uint32_t af[4][4], bf[4][2];
#pragma unroll
            for (int mi = 0; mi < 4; ++mi) {
                int r = warpM * 64 + mi * 16 + (lane & 15);
                int g = kk * 2 + (lane >> 4);
                uint32_t addr = smem + s * 16384 + r * 128 + ((g ^ (r & 7)) << 4);
                asm volatile("ldmatrix.sync.aligned.m8n8.x4.shared.b16 {%0,%1,%2,%3}, [%4];\n"
                    : "=r"(af[mi][0]), "=r"(af[mi][1]), "=r"(af[mi][2]), "=r"(af[mi][3])
                    : "r"(addr));
            }
#pragma unroll
            for (int ni = 0; ni < 4; ++ni) {
                int r = warpN * 32 + ni * 8 + (lane & 7);
                int g = kk * 2 + ((lane >> 3) & 1);
                uint32_t addr = smem + 32768 + s * 16384 + r * 128 + ((g ^ (r & 7)) << 4);
                asm volatile("ldmatrix.sync.aligned.m8n8.x2.shared.b16 {%0,%1}, [%2];\n"
                    : "=r"(bf[ni][0]), "=r"(bf[ni][1]) : "r"(addr));
            }
#pragma unroll
            for (int mi = 0; mi < 4; ++mi)
#pragma unroll
                for (int ni = 0; ni < 4; ++ni) {
                    asm volatile(
                        "mma.sync.aligned.m16n8k16.row.col.f32.bf16.bf16.f32 "
                        "{%0,%1,%2,%3}, {%4,%5,%6,%7}, {%8,%9}, {%0,%1,%2,%3};\n"
                        : "+f"(acc[mi][ni][0]), "+f"(acc[mi][ni][1]),
                          "+f"(acc[mi][ni][2]), "+f"(acc[mi][ni][3])
                        : "r"(af[mi][0]), "r"(af[mi][1]), "r"(af[mi][2]), "r"(af[mi][3]),
                          "r"(bf[ni][0]), "r"(bf[ni][1]));
                }
        }
    }

    // direct store of tile (mb, nb)
    float* Cg = g_dist + ((size_t)b * N_DIM + mBase) * N_DIM + nBase;
#pragma unroll
    for (int mi = 0; mi < 4; ++mi)
#pragma unroll
        for (int ni = 0; ni < 4; ++ni) {
            int r0 = warpM * 64 + mi * 16 + (lane >> 2);
            int c0 = warpN * 32 + ni * 8 + 2 * (lane & 3);
            float2 v01 = make_float2(acc[mi][ni][0], acc[mi][ni][1]);
            float2 v23 = make_float2(acc[mi][ni][2], acc[mi][ni][3]);
            *(float2*)(Cg + (size_t)r0 * N_DIM + c0) = v01;
            *(float2*)(Cg + (size_t)(r0 + 8) * N_DIM + c0) = v23;
        }

    if (mb != nb) {
        // transposed store of the same accumulators into tile (nb, mb):
        // stage into smem as smf[c * 132 + r] (conflict-free: bank index
        // 8*(lane&3) + (lane>>2) spans all 32 banks), read back coalesced.
        float* smf = (float*)sm;
        __syncthreads();   // done with A/B buffers
#pragma unroll
        for (int mi = 0; mi < 4; ++mi)
#pragma unroll
            for (int ni = 0; ni < 4; ++ni) {
                int r0 = warpM * 64 + mi * 16 + (lane >> 2);
                int c0 = warpN * 32 + ni * 8 + 2 * (lane & 3);
                smf[c0 * 132 + r0]           = acc[mi][ni][0];
                smf[(c0 + 1) * 132 + r0]     = acc[mi][ni][1];
                smf[c0 * 132 + r0 + 8]       = acc[mi][ni][2];
                smf[(c0 + 1) * 132 + r0 + 8] = acc[mi][ni][3];
            }
        __syncthreads();
        float* Ct = g_dist + ((size_t)b * N_DIM + nBase) * N_DIM + mBase;
        for (int idx = tid; idx < 128 * 32; idx += 256) {
            int row = idx >> 5;       // column of C = row of C^T
            int c4  = idx & 31;
            float4 v = *(const float4*)(smf + row * 132 + c4 * 4);
            *(float4*)(Ct + (size_t)row * N_DIM + c4 * 4) = v;
        }
    }
}

// ---------------------------------------------------------------------------
// Kernel 4: warp-per-row approximate top-8 candidate selection (indices only).
// float4 loads, single threshold compare per element, warp-shuffle argmax-pop
// merge (no smem, no serial lane-0 scan).
// ---------------------------------------------------------------------------
__global__ void __launch_bounds__(256) k_topk(void) {
    const unsigned FULL = 0xffffffffu;
    int w = threadIdx.x >> 5;
    int lane = threadIdx.x & 31;
    int gw = blockIdx.x * 8 + w;              // global row id over B*N
    const float4* row = (const float4*)(g_dist + (size_t)gw * N_DIM);

    float tv[CAND];
    int   ti[CAND];
#pragma unroll
    for (int s = 0; s < CAND; ++s) { tv[s] = -3.4e38f; ti[s] = -1; }

#define INS(VAL, J)                                                     \
    if ((VAL) > tv[CAND - 1]) {                                         \
        tv[CAND - 1] = (VAL); ti[CAND - 1] = (J);                       \
        _Pragma("unroll")                                               \
        for (int s = CAND - 1; s > 0; --s)                              \
            if (tv[s] > tv[s - 1]) {                                    \
                float a = tv[s]; tv[s] = tv[s - 1]; tv[s - 1] = a;      \
                int   c = ti[s]; ti[s] = ti[s - 1]; ti[s - 1] = c;      \
            }                                                           \
    }

#pragma unroll
    for (int i = 0; i < N_DIM / 128; ++i) {   // 16 float4s per lane
        float4 v = row[lane + i * 32];
        int jb = 4 * (lane + i * 32);
        INS(v.x, jb)
        INS(v.y, jb + 1)
        INS(v.z, jb + 2)
        INS(v.w, jb + 3)
    }
#undef INS

    // Warp merge: 8 rounds of argmax over lane heads, winner pops its list.
    int out_idx[CAND];
#pragma unroll
    for (int s = 0; s < CAND; ++s) {
        float best = tv[0];
        int bl = lane;
#pragma unroll
        for (int o = 16; o; o >>= 1) {
            float ov = __shfl_xor_sync(FULL, best, o);
            int obl = __shfl_xor_sync(FULL, bl, o);
            if (ov > best || (ov == best && obl < bl)) { best = ov; bl = obl; }
        }
        int bi = __shfl_sync(FULL, ti[0], bl);
        out_idx[s] = bi;
        if (lane == bl) {
#pragma unroll
            for (int q = 0; q < CAND - 1; ++q) { tv[q] = tv[q + 1]; ti[q] = ti[q + 1]; }
            tv[CAND - 1] = -3.4e38f;
        }
    }
    if (lane < CAND) g_cand[(size_t)gw * CAND + lane] = out_idx[lane];
}

// ---------------------------------------------------------------------------
// Kernel 5: exact fp32 re-ranking of the 8 candidates + symmetric scatter.
// Lane-strided sum + shfl tree is bit-identical for (r,j) and (j,r).
// ---------------------------------------------------------------------------
__global__ void __launch_bounds__(256) k_refine(float* __restrict__ out) {
    int rowid = blockIdx.x;
    int b = rowid >> 11, r = rowid & (N_DIM - 1);
    __shared__ float srow[TD];
    __shared__ float sdot[CAND];
    __shared__ int   sjj[CAND];
    const float* xr = g_xf + (size_t)rowid * TD;
    for (int i = threadIdx.x; i < TD; i += 256) srow[i] = xr[i];
    __syncthreads();

    int w = threadIdx.x >> 5, lane = threadIdx.x & 31;
    int j = g_cand[(size_t)rowid * CAND + w];
    const float* xj = g_xf + ((size_t)(b << 11) + j) * TD;
    float s = 0.f;
#pragma unroll
    for (int i = 0; i < TD / 32; ++i)
        s = fmaf(srow[lane + i * 32], xj[lane + i * 32], s);
#pragma unroll
    for (int o = 16; o; o >>= 1) s += __shfl_xor_sync(0xffffffffu, s, o);
    if (lane == 0) { sdot[w] = s; sjj[w] = j; }
    __syncthreads();

    if (threadIdx.x == 0) {
        float tv[5]; int ti[5];
#pragma unroll
        for (int q = 0; q < 5; ++q) { tv[q] = -3.4e38f; ti[q] = 0; }
        for (int c = 0; c < CAND; ++c) {
            float val = sdot[c]; int jj = sjj[c];
            if (val > tv[4]) {
                tv[4] = val; ti[4] = jj;
#pragma unroll
                for (int q = 4; q > 0; --q) {
                    if (tv[q] > tv[q - 1]) {
                        float a = tv[q]; tv[q] = tv[q - 1]; tv[q - 1] = a;
                        int   d2 = ti[q]; ti[q] = ti[q - 1]; ti[q - 1] = d2;
                    }
                }
            }
        }
#pragma unroll
        for (int q = 0; q < 5; ++q) {
            float val = tv[q];
            int jj = ti[q];
            float lv = (val >= 0.f) ? val : 0.01f * val;  // leaky_relu
            float wgt = lv * 0.5f;                        // symmetric halves
            atomicAdd(out + ((size_t)b * N_DIM + r) * N_DIM + jj, wgt);
            atomicAdd(out + ((size_t)b * N_DIM + jj) * N_DIM + r, wgt);
        }
    }
}

// ---------------------------------------------------------------------------
extern "C" void kernel_launch(void* const* d_in, const int* in_sizes, int n_in,
                              void* d_out, int out_size) {
    const float* x = (const float*)d_in[0];
    float* out = (float*)d_out;

    k_normalize<<<B_DIM * N_DIM, 128>>>(x);

    size_t n4 = (size_t)B_DIM * N_DIM * N_DIM / 4;
    k_zero<<<8192, 256>>>((float4*)out, n4);

    cudaFuncSetAttribute(k_gemm, cudaFuncAttributeMaxDynamicSharedMemorySize, SMEM_BYTES);
    k_gemm<<<dim3(NUT, 1, B_DIM), 256, SMEM_BYTES>>>();

    k_topk<<<(B_DIM * N_DIM) / 8, 256>>>();

    k_refine<<<B_DIM * N_DIM, 256>>>(out);
}